// round 2
// baseline (speedup 1.0000x reference)
#include <cuda_runtime.h>
#include <math.h>

#define NTOK 4096
#define DIM  1024
#define HID  4096
#define NEXP 8
#define TOPK 2
#define NASSIGN (NTOK * TOPK)   // 8192

// ---------------- scratch (static device globals; no allocations) ----------
__device__ int   g_cnt[NEXP];
__device__ int   g_off[NEXP];
__device__ int   g_fill[NEXP];
__device__ int   g_texp[NASSIGN];
__device__ float g_twt[NASSIGN];
__device__ int   g_rowtok[NASSIGN];   // grouped-by-expert token index
__device__ float g_rowwt[NASSIGN];    // grouped-by-expert gate weight
__device__ int   g_tokrow[NASSIGN];   // (token,slot) -> grouped row id
__device__ float g_hbuf[(size_t)NASSIGN * HID];  // 128 MB hidden activations
__device__ float g_part[(size_t)NASSIGN * DIM];  // 32 MB per-assignment outputs

// ---------------- reset -----------------------------------------------------
__global__ void reset_kernel() {
    int t = threadIdx.x;
    if (t < NEXP) { g_cnt[t] = 0; g_fill[t] = 0; }
}

// ---------------- gating: logits, top-2 softmax, counts ---------------------
__global__ void gating_kernel(const float* __restrict__ x,
                              const float* __restrict__ gw,
                              const float* __restrict__ gb,
                              float* __restrict__ out_logits) {
    const int n = blockIdx.x;
    const float* xr = x + (size_t)n * DIM;
    float acc[NEXP];
#pragma unroll
    for (int e = 0; e < NEXP; e++) acc[e] = 0.f;

    for (int d = threadIdx.x; d < DIM; d += blockDim.x) {
        float xv = xr[d];
        const float* g = gw + (size_t)d * NEXP;
#pragma unroll
        for (int e = 0; e < NEXP; e++) acc[e] = fmaf(xv, g[e], acc[e]);
    }

    __shared__ float red[256][NEXP];
#pragma unroll
    for (int e = 0; e < NEXP; e++) red[threadIdx.x][e] = acc[e];
    __syncthreads();
    for (int s = 128; s > 0; s >>= 1) {
        if (threadIdx.x < s) {
#pragma unroll
            for (int e = 0; e < NEXP; e++)
                red[threadIdx.x][e] += red[threadIdx.x + s][e];
        }
        __syncthreads();
    }

    if (threadIdx.x == 0) {
        float l[NEXP];
#pragma unroll
        for (int e = 0; e < NEXP; e++) {
            l[e] = red[0][e] + gb[e];
            out_logits[(size_t)n * NEXP + e] = l[e];
        }
        // top-2, lowest index wins ties (matches jax.lax.top_k)
        int i0 = 0;
#pragma unroll
        for (int e = 1; e < NEXP; e++) if (l[e] > l[i0]) i0 = e;
        int i1 = -1;
#pragma unroll
        for (int e = 0; e < NEXP; e++)
            if (e != i0 && (i1 < 0 || l[e] > l[i1])) i1 = e;
        // softmax over the 2 selected (l[i0] >= l[i1])
        float ex = __expf(l[i1] - l[i0]);
        float w0 = 1.f / (1.f + ex);
        float w1 = ex / (1.f + ex);
        g_texp[n * 2 + 0] = i0;  g_twt[n * 2 + 0] = w0;
        g_texp[n * 2 + 1] = i1;  g_twt[n * 2 + 1] = w1;
        atomicAdd(&g_cnt[i0], 1);
        atomicAdd(&g_cnt[i1], 1);
    }
}

// ---------------- exclusive prefix of counts --------------------------------
__global__ void offsets_kernel() {
    if (threadIdx.x == 0) {
        int s = 0;
        for (int e = 0; e < NEXP; e++) { g_off[e] = s; s += g_cnt[e]; }
    }
}

// ---------------- build grouped token lists ---------------------------------
__global__ void fill_kernel() {
    int n = blockIdx.x * blockDim.x + threadIdx.x;
    if (n >= NTOK) return;
#pragma unroll
    for (int s = 0; s < TOPK; s++) {
        int e = g_texp[n * 2 + s];
        float w = g_twt[n * 2 + s];
        int pos = atomicAdd(&g_fill[e], 1);
        int row = g_off[e] + pos;
        g_rowtok[row] = n;
        g_rowwt[row]  = w;
        g_tokrow[n * 2 + s] = row;
    }
}

// ---------------- grouped GEMM1: h = gelu(w*x @ W1 + b1) --------------------
// 128x128x16 tile, 256 threads, 8x8 per thread
__global__ __launch_bounds__(256)
void gemm1_kernel(const float* __restrict__ x,
                  const float* __restrict__ w1,
                  const float* __restrict__ b1) {
    const int e   = blockIdx.z;
    const int cnt = g_cnt[e];
    const int m0  = blockIdx.y * 128;
    if (m0 >= cnt) return;
    const int n0   = blockIdx.x * 128;
    const int base = g_off[e];
    const float* W = w1 + (size_t)e * DIM * HID;

    __shared__ float As[16][128];
    __shared__ float Bs[16][128];

    const int tid = threadIdx.x;
    // A loader: thread -> (row ar, col start ac in {0,8})
    const int ar = tid >> 1;
    const int ac = (tid & 1) * 8;
    const int arow = m0 + ar;
    const float* xrow = nullptr;
    float wt = 0.f;
    if (arow < cnt) {
        int tok = g_rowtok[base + arow];
        wt   = g_rowwt[base + arow];
        xrow = x + (size_t)tok * DIM;
    }
    // B loader: thread -> rows br, br+8, 4 cols at bc
    const int br = tid >> 5;
    const int bc = (tid & 31) * 4;

    float acc[8][8];
#pragma unroll
    for (int i = 0; i < 8; i++)
#pragma unroll
        for (int j = 0; j < 8; j++) acc[i][j] = 0.f;

    const int tx = (tid & 15) * 8;
    const int ty = (tid >> 4) * 8;

    for (int k0 = 0; k0 < DIM; k0 += 16) {
        float4 a0 = make_float4(0.f, 0.f, 0.f, 0.f), a1 = a0;
        if (xrow) {
            a0 = *(const float4*)(xrow + k0 + ac);
            a1 = *(const float4*)(xrow + k0 + ac + 4);
        }
        As[ac + 0][ar] = a0.x * wt; As[ac + 1][ar] = a0.y * wt;
        As[ac + 2][ar] = a0.z * wt; As[ac + 3][ar] = a0.w * wt;
        As[ac + 4][ar] = a1.x * wt; As[ac + 5][ar] = a1.y * wt;
        As[ac + 6][ar] = a1.z * wt; As[ac + 7][ar] = a1.w * wt;

        *(float4*)&Bs[br][bc]     = *(const float4*)(W + (size_t)(k0 + br) * HID + n0 + bc);
        *(float4*)&Bs[br + 8][bc] = *(const float4*)(W + (size_t)(k0 + br + 8) * HID + n0 + bc);
        __syncthreads();

#pragma unroll
        for (int k = 0; k < 16; k++) {
            float4 aA = *(const float4*)&As[k][ty];
            float4 aB = *(const float4*)&As[k][ty + 4];
            float4 bA = *(const float4*)&Bs[k][tx];
            float4 bB = *(const float4*)&Bs[k][tx + 4];
            float a[8] = {aA.x, aA.y, aA.z, aA.w, aB.x, aB.y, aB.z, aB.w};
            float b[8] = {bA.x, bA.y, bA.z, bA.w, bB.x, bB.y, bB.z, bB.w};
#pragma unroll
            for (int i = 0; i < 8; i++)
#pragma unroll
                for (int j = 0; j < 8; j++)
                    acc[i][j] = fmaf(a[i], b[j], acc[i][j]);
        }
        __syncthreads();
    }

    // epilogue: + b1, exact-erf gelu, store hidden
#pragma unroll
    for (int i = 0; i < 8; i++) {
        int r = m0 + ty + i;
        if (r < cnt) {
            float* hp = g_hbuf + (size_t)(base + r) * HID + n0 + tx;
            const float* bp = b1 + (size_t)e * HID + n0 + tx;
#pragma unroll
            for (int j = 0; j < 8; j++) {
                float v = acc[i][j] + bp[j];
                v = 0.5f * v * (1.f + erff(v * 0.70710678118654752f));
                hp[j] = v;
            }
        }
    }
}

// ---------------- grouped GEMM2: part = w * (h @ W2 + b2) -------------------
__global__ __launch_bounds__(256)
void gemm2_kernel(const float* __restrict__ w2,
                  const float* __restrict__ b2) {
    const int e   = blockIdx.z;
    const int cnt = g_cnt[e];
    const int m0  = blockIdx.y * 128;
    if (m0 >= cnt) return;
    const int n0   = blockIdx.x * 128;
    const int base = g_off[e];
    const float* W = w2 + (size_t)e * HID * DIM;

    __shared__ float As[16][128];
    __shared__ float Bs[16][128];

    const int tid = threadIdx.x;
    const int ar = tid >> 1;
    const int ac = (tid & 1) * 8;
    const int arow = m0 + ar;
    const float* hrow = (arow < cnt) ? (g_hbuf + (size_t)(base + arow) * HID) : nullptr;

    const int br = tid >> 5;
    const int bc = (tid & 31) * 4;

    float acc[8][8];
#pragma unroll
    for (int i = 0; i < 8; i++)
#pragma unroll
        for (int j = 0; j < 8; j++) acc[i][j] = 0.f;

    const int tx = (tid & 15) * 8;
    const int ty = (tid >> 4) * 8;

    for (int k0 = 0; k0 < HID; k0 += 16) {
        float4 a0 = make_float4(0.f, 0.f, 0.f, 0.f), a1 = a0;
        if (hrow) {
            a0 = *(const float4*)(hrow + k0 + ac);
            a1 = *(const float4*)(hrow + k0 + ac + 4);
        }
        As[ac + 0][ar] = a0.x; As[ac + 1][ar] = a0.y;
        As[ac + 2][ar] = a0.z; As[ac + 3][ar] = a0.w;
        As[ac + 4][ar] = a1.x; As[ac + 5][ar] = a1.y;
        As[ac + 6][ar] = a1.z; As[ac + 7][ar] = a1.w;

        *(float4*)&Bs[br][bc]     = *(const float4*)(W + (size_t)(k0 + br) * DIM + n0 + bc);
        *(float4*)&Bs[br + 8][bc] = *(const float4*)(W + (size_t)(k0 + br + 8) * DIM + n0 + bc);
        __syncthreads();

#pragma unroll
        for (int k = 0; k < 16; k++) {
            float4 aA = *(const float4*)&As[k][ty];
            float4 aB = *(const float4*)&As[k][ty + 4];
            float4 bA = *(const float4*)&Bs[k][tx];
            float4 bB = *(const float4*)&Bs[k][tx + 4];
            float a[8] = {aA.x, aA.y, aA.z, aA.w, aB.x, aB.y, aB.z, aB.w};
            float b[8] = {bA.x, bA.y, bA.z, bA.w, bB.x, bB.y, bB.z, bB.w};
#pragma unroll
            for (int i = 0; i < 8; i++)
#pragma unroll
                for (int j = 0; j < 8; j++)
                    acc[i][j] = fmaf(a[i], b[j], acc[i][j]);
        }
        __syncthreads();
    }

#pragma unroll
    for (int i = 0; i < 8; i++) {
        int r = m0 + ty + i;
        if (r < cnt) {
            float rw = g_rowwt[base + r];
            float* pp = g_part + (size_t)(base + r) * DIM + n0 + tx;
            const float* bp = b2 + (size_t)e * DIM + n0 + tx;
#pragma unroll
            for (int j = 0; j < 8; j++)
                pp[j] = (acc[i][j] + bp[j]) * rw;
        }
    }
}

// ---------------- combine the two expert contributions ----------------------
__global__ void combine_kernel(float* __restrict__ out) {
    int idx = blockIdx.x * blockDim.x + threadIdx.x;  // float4 index over NTOK*DIM
    int n  = idx >> 8;            // DIM/4 = 256 float4 per token
    int d4 = (idx & 255) * 4;
    int r0 = g_tokrow[n * 2 + 0];
    int r1 = g_tokrow[n * 2 + 1];
    float4 p = *(const float4*)(g_part + (size_t)r0 * DIM + d4);
    float4 q = *(const float4*)(g_part + (size_t)r1 * DIM + d4);
    float4 o = make_float4(p.x + q.x, p.y + q.y, p.z + q.z, p.w + q.w);
    *(float4*)(out + (size_t)n * DIM + d4) = o;
}

// ---------------- launch -----------------------------------------------------
extern "C" void kernel_launch(void* const* d_in, const int* in_sizes, int n_in,
                              void* d_out, int out_size) {
    const float* x  = (const float*)d_in[0];
    const float* gw = (const float*)d_in[1];
    const float* gb = (const float*)d_in[2];
    const float* w1 = (const float*)d_in[3];
    const float* b1 = (const float*)d_in[4];
    const float* w2 = (const float*)d_in[5];
    const float* b2 = (const float*)d_in[6];

    float* out_final  = (float*)d_out;
    float* out_logits = out_final + (size_t)NTOK * DIM;

    reset_kernel<<<1, 32>>>();
    gating_kernel<<<NTOK, 256>>>(x, gw, gb, out_logits);
    offsets_kernel<<<1, 1>>>();
    fill_kernel<<<(NTOK + 255) / 256, 256>>>();
    gemm1_kernel<<<dim3(HID / 128, NTOK / 128, NEXP), 256>>>(x, w1, b1);
    gemm2_kernel<<<dim3(DIM / 128, NTOK / 128, NEXP), 256>>>(w2, b2);
    combine_kernel<<<(NTOK * DIM / 4) / 256, 256>>>(out_final);
}

// round 5
// speedup vs baseline: 4.8669x; 4.8669x over previous
#include <cuda_runtime.h>
#include <cstdint>
#include <math.h>

#define NTOK 4096
#define DIM  1024
#define HID  4096
#define NEXP 8
#define TOPK 2
#define NASSIGN (NTOK * TOPK)        // 8192
#define ROWPAD  (NASSIGN + 128)      // pad rows for ragged M-tiles (zero-init)

// ---------------- scratch (static device globals; no allocations) -----------
__device__ int   g_cnt[NEXP];
__device__ int   g_off[NEXP];
__device__ int   g_fill[NEXP];
__device__ int   g_texp[NASSIGN];
__device__ float g_twt[NASSIGN];
__device__ int   g_rowtok[NASSIGN];
__device__ float g_rowwt[NASSIGN];
__device__ int   g_tokrow[NASSIGN];
__device__ float g_xg  [(size_t)ROWPAD * DIM];   // gathered, gate-weighted x
__device__ float g_hbuf[(size_t)ROWPAD * HID];   // hidden activations
__device__ float g_part[(size_t)NASSIGN * DIM];  // per-assignment outputs

// ---------------- helpers ----------------------------------------------------
__device__ __forceinline__ uint32_t smem_u32(const void* p) {
    uint32_t a;
    asm("{ .reg .u64 t; cvta.to.shared.u64 t, %1; cvt.u32.u64 %0, t; }" : "=r"(a) : "l"(p));
    return a;
}
__device__ __forceinline__ uint32_t f2tf(float v) {
    uint32_t r;
    asm("cvt.rna.tf32.f32 %0, %1;" : "=r"(r) : "f"(v));
    return r;
}
__device__ __forceinline__ void mma_tf32(float* d, const uint32_t* a, const uint32_t* b) {
    asm volatile(
        "mma.sync.aligned.m16n8k8.row.col.f32.tf32.tf32.f32 "
        "{%0,%1,%2,%3}, {%4,%5,%6,%7}, {%8,%9}, {%0,%1,%2,%3};"
        : "+f"(d[0]), "+f"(d[1]), "+f"(d[2]), "+f"(d[3])
        : "r"(a[0]), "r"(a[1]), "r"(a[2]), "r"(a[3]), "r"(b[0]), "r"(b[1]));
}
__device__ __forceinline__ void cpasync16(uint32_t dst, const void* src) {
    asm volatile("cp.async.cg.shared.global [%0], [%1], 16;" :: "r"(dst), "l"(src) : "memory");
}
#define CP_COMMIT() asm volatile("cp.async.commit_group;" ::: "memory")
#define CP_WAIT(n)  asm volatile("cp.async.wait_group %0;" :: "n"(n) : "memory")

// ---------------- routing kernels -------------------------------------------
__global__ void reset_kernel() {
    int t = threadIdx.x;
    if (t < NEXP) { g_cnt[t] = 0; g_fill[t] = 0; }
}

__global__ void gating_kernel(const float* __restrict__ x,
                              const float* __restrict__ gw,
                              const float* __restrict__ gb,
                              float* __restrict__ out_logits) {
    const int n = blockIdx.x;
    const float* xr = x + (size_t)n * DIM;
    float acc[NEXP];
#pragma unroll
    for (int e = 0; e < NEXP; e++) acc[e] = 0.f;
    for (int d = threadIdx.x; d < DIM; d += blockDim.x) {
        float xv = xr[d];
        const float* g = gw + (size_t)d * NEXP;
#pragma unroll
        for (int e = 0; e < NEXP; e++) acc[e] = fmaf(xv, g[e], acc[e]);
    }
    __shared__ float red[256][NEXP];
#pragma unroll
    for (int e = 0; e < NEXP; e++) red[threadIdx.x][e] = acc[e];
    __syncthreads();
    for (int s = 128; s > 0; s >>= 1) {
        if (threadIdx.x < s)
#pragma unroll
            for (int e = 0; e < NEXP; e++) red[threadIdx.x][e] += red[threadIdx.x + s][e];
        __syncthreads();
    }
    if (threadIdx.x == 0) {
        float l[NEXP];
#pragma unroll
        for (int e = 0; e < NEXP; e++) {
            l[e] = red[0][e] + gb[e];
            out_logits[(size_t)n * NEXP + e] = l[e];
        }
        int i0 = 0;
#pragma unroll
        for (int e = 1; e < NEXP; e++) if (l[e] > l[i0]) i0 = e;
        int i1 = -1;
#pragma unroll
        for (int e = 0; e < NEXP; e++)
            if (e != i0 && (i1 < 0 || l[e] > l[i1])) i1 = e;
        float ex = __expf(l[i1] - l[i0]);
        float w0 = 1.f / (1.f + ex);
        float w1 = ex / (1.f + ex);
        g_texp[n * 2 + 0] = i0; g_twt[n * 2 + 0] = w0;
        g_texp[n * 2 + 1] = i1; g_twt[n * 2 + 1] = w1;
        atomicAdd(&g_cnt[i0], 1);
        atomicAdd(&g_cnt[i1], 1);
    }
}

__global__ void offsets_kernel() {
    if (threadIdx.x == 0) {
        int s = 0;
        for (int e = 0; e < NEXP; e++) { g_off[e] = s; s += g_cnt[e]; }
    }
}

__global__ void fill_kernel() {
    int n = blockIdx.x * blockDim.x + threadIdx.x;
    if (n >= NTOK) return;
#pragma unroll
    for (int s = 0; s < TOPK; s++) {
        int e = g_texp[n * 2 + s];
        int pos = atomicAdd(&g_fill[e], 1);
        int row = g_off[e] + pos;
        g_rowtok[row] = n;
        g_rowwt[row]  = g_twt[n * 2 + s];
        g_tokrow[n * 2 + s] = row;
    }
}

// gather + gate-weight: xg[row] = x[tok] * wt
__global__ void gather_kernel(const float* __restrict__ x) {
    int row = blockIdx.x;
    int tok = g_rowtok[row];
    float wt = g_rowwt[row];
    const float4* xp = (const float4*)(x + (size_t)tok * DIM);
    float4* gp = (float4*)(g_xg + (size_t)row * DIM);
    float4 v = xp[threadIdx.x];
    v.x *= wt; v.y *= wt; v.z *= wt; v.w *= wt;
    gp[threadIdx.x] = v;
}

// ---------------- tf32 mma.sync grouped GEMM --------------------------------
// CTA tile 128(M) x 128(N) x 32(K), 8 warps (2x4), warp tile 64x32.
// 3-stage cp.async pipeline. A = grouped rows (g_xg / g_hbuf), K-major.
// B = w1/w2 slices, global row-major [K][N] -> col-frag layout of mma.
// MODE 0: out = gelu(acc + b1) -> g_hbuf ; MODE 1: out = (acc + b2)*wt -> g_part
#define AP 36                        // A smem pitch (floats)
#define BP 132                       // B smem pitch (floats)
#define ABYTES (128 * AP * 4)        // 18432
#define BBYTES (32 * BP * 4)         // 16896
#define STAGE_B (ABYTES + BBYTES)    // 35328
#define NSTAGE 3
#define GEMM_SMEM (NSTAGE * STAGE_B) // 105984

template <int KD, int NB, int MODE>
__global__ __launch_bounds__(256)
void gemm_tc(const float* __restrict__ Abase,
             const float* __restrict__ W,
             const float* __restrict__ bias) {
    const int e   = blockIdx.z;
    const int cnt = g_cnt[e];
    const int m0  = blockIdx.y * 128;
    if (m0 >= cnt) return;
    const int n0   = blockIdx.x * 128;
    const int base = g_off[e];
    constexpr int NC = KD / 32;

    extern __shared__ char smem[];
    const uint32_t sb = smem_u32(smem);
    const int tid  = threadIdx.x;
    const int wid  = tid >> 5;
    const int lane = tid & 31;

    const float* Wg = W + (size_t)e * KD * NB;
    const float* Ag = Abase + (size_t)(base + m0) * KD;

    // cp.async source/dest coordinates
    const int arow = tid >> 3, acol = (tid & 7) * 4;   // A: 32 rows/wave, 4 waves
    const int brow = tid >> 5, bcol = (tid & 31) * 4;  // B: 8 rows/wave, 4 waves

    auto load_chunk = [&](int c, int st) {
        const uint32_t sa = sb + st * STAGE_B;
#pragma unroll
        for (int w = 0; w < 4; w++) {
            int r = arow + w * 32;
            cpasync16(sa + (r * AP + acol) * 4, Ag + (size_t)r * KD + c * 32 + acol);
        }
        const uint32_t sB = sa + ABYTES;
#pragma unroll
        for (int w = 0; w < 4; w++) {
            int r = brow + w * 8;
            cpasync16(sB + (r * BP + bcol) * 4, Wg + (size_t)(c * 32 + r) * NB + n0 + bcol);
        }
        CP_COMMIT();
    };

    float acc[4][4][4];
#pragma unroll
    for (int i = 0; i < 4; i++)
#pragma unroll
        for (int j = 0; j < 4; j++)
#pragma unroll
            for (int k = 0; k < 4; k++) acc[i][j][k] = 0.f;

    const int mbase = (wid & 1) * 64;
    const int nbase = (wid >> 1) * 32;
    const int ra = lane >> 2, ca = lane & 3;

    load_chunk(0, 0);
    load_chunk(1, 1);

    for (int c = 0; c < NC; c++) {
        if (c + 2 < NC) load_chunk(c + 2, (c + 2) % NSTAGE);
        CP_WAIT(1);
        __syncthreads();

        const float* As = (const float*)(smem + (c % NSTAGE) * STAGE_B);
        const float* Bs = (const float*)(smem + (c % NSTAGE) * STAGE_B + ABYTES);

#pragma unroll
        for (int kk = 0; kk < 4; kk++) {
            uint32_t a[4][4], b[4][2];
#pragma unroll
            for (int mt = 0; mt < 4; mt++) {
                const float* ap = As + (mbase + mt * 16 + ra) * AP + kk * 8 + ca;
                a[mt][0] = f2tf(ap[0]);
                a[mt][1] = f2tf(ap[8 * AP]);
                a[mt][2] = f2tf(ap[4]);
                a[mt][3] = f2tf(ap[8 * AP + 4]);
            }
#pragma unroll
            for (int nt = 0; nt < 4; nt++) {
                const float* bp = Bs + (kk * 8 + ca) * BP + nbase + nt * 8 + ra;
                b[nt][0] = f2tf(bp[0]);
                b[nt][1] = f2tf(bp[4 * BP]);
            }
#pragma unroll
            for (int mt = 0; mt < 4; mt++)
#pragma unroll
                for (int nt = 0; nt < 4; nt++)
                    mma_tf32(acc[mt][nt], a[mt], b[nt]);
        }
        __syncthreads();
    }

    // epilogue
    const float* bp = bias + (size_t)e * NB + n0;
    float* Obase = (MODE == 0 ? g_hbuf : g_part);
#pragma unroll
    for (int mt = 0; mt < 4; mt++) {
#pragma unroll
        for (int half = 0; half < 2; half++) {
            int r = m0 + mbase + mt * 16 + ra + half * 8;
            if (r < cnt) {
                float wt = (MODE == 1) ? g_rowwt[base + r] : 0.f;
                float* op = Obase + (size_t)(base + r) * NB + n0;
#pragma unroll
                for (int nt = 0; nt < 4; nt++) {
                    int col = nbase + nt * 8 + ca * 2;
                    float v0 = acc[mt][nt][half * 2 + 0] + bp[col];
                    float v1 = acc[mt][nt][half * 2 + 1] + bp[col + 1];
                    float2 v;
                    if (MODE == 0) {
                        v.x = 0.5f * v0 * (1.f + erff(v0 * 0.70710678118654752f));
                        v.y = 0.5f * v1 * (1.f + erff(v1 * 0.70710678118654752f));
                    } else {
                        v.x = v0 * wt;
                        v.y = v1 * wt;
                    }
                    *(float2*)(op + col) = v;
                }
            }
        }
    }
}

// ---------------- combine ----------------------------------------------------
__global__ void combine_kernel(float* __restrict__ out) {
    int idx = blockIdx.x * blockDim.x + threadIdx.x;
    int n  = idx >> 8;
    int d4 = (idx & 255) * 4;
    int r0 = g_tokrow[n * 2 + 0];
    int r1 = g_tokrow[n * 2 + 1];
    float4 p = *(const float4*)(g_part + (size_t)r0 * DIM + d4);
    float4 q = *(const float4*)(g_part + (size_t)r1 * DIM + d4);
    *(float4*)(out + (size_t)n * DIM + d4) =
        make_float4(p.x + q.x, p.y + q.y, p.z + q.z, p.w + q.w);
}

// ---------------- host -------------------------------------------------------
extern "C" void kernel_launch(void* const* d_in, const int* in_sizes, int n_in,
                              void* d_out, int out_size) {
    const float* x  = (const float*)d_in[0];
    const float* gw = (const float*)d_in[1];
    const float* gb = (const float*)d_in[2];
    const float* w1 = (const float*)d_in[3];
    const float* b1 = (const float*)d_in[4];
    const float* w2 = (const float*)d_in[5];
    const float* b2 = (const float*)d_in[6];

    float* out_final  = (float*)d_out;
    float* out_logits = out_final + (size_t)NTOK * DIM;

    void *p_xg, *p_hb;
    cudaGetSymbolAddress(&p_xg, g_xg);
    cudaGetSymbolAddress(&p_hb, g_hbuf);

    cudaFuncSetAttribute(gemm_tc<DIM, HID, 0>, cudaFuncAttributeMaxDynamicSharedMemorySize, GEMM_SMEM);
    cudaFuncSetAttribute(gemm_tc<HID, DIM, 1>, cudaFuncAttributeMaxDynamicSharedMemorySize, GEMM_SMEM);

    reset_kernel<<<1, 32>>>();
    gating_kernel<<<NTOK, 256>>>(x, gw, gb, out_logits);
    offsets_kernel<<<1, 1>>>();
    fill_kernel<<<(NTOK + 255) / 256, 256>>>();
    gather_kernel<<<NASSIGN, 256>>>(x);
    gemm_tc<DIM, HID, 0><<<dim3(HID / 128, NTOK / 128, NEXP), 256, GEMM_SMEM>>>(
        (const float*)p_xg, w1, b1);
    gemm_tc<HID, DIM, 1><<<dim3(DIM / 128, NTOK / 128, NEXP), 256, GEMM_SMEM>>>(
        (const float*)p_hb, w2, b2);
    combine_kernel<<<(NTOK * DIM / 4) / 256, 256>>>(out_final);
}

// round 7
// speedup vs baseline: 5.2728x; 1.0834x over previous
#include <cuda_runtime.h>
#include <cstdint>
#include <math.h>

#define NTOK 4096
#define DIM  1024
#define HID  4096
#define NEXP 8
#define TOPK 2
#define NASSIGN (NTOK * TOPK)        // 8192
#define ROWPAD  (NASSIGN + 128)      // pad rows for ragged M-tiles (zero-init)

// ---------------- scratch (static device globals; no allocations) -----------
__device__ int   g_cnt[NEXP];
__device__ int   g_off[NEXP];
__device__ int   g_fill[NEXP];
__device__ int   g_texp[NASSIGN];
__device__ float g_twt[NASSIGN];
__device__ int   g_rowtok[NASSIGN];
__device__ float g_rowwt[NASSIGN];
__device__ int   g_tokrow[NASSIGN];
__device__ float g_xg  [(size_t)ROWPAD * DIM];   // gathered, weighted, tf32-rounded x
__device__ float g_hbuf[(size_t)ROWPAD * HID];   // hidden activations (tf32-rounded)
__device__ float g_part[(size_t)NASSIGN * DIM];  // per-assignment outputs

// ---------------- helpers ----------------------------------------------------
__device__ __forceinline__ uint32_t f2tf(float v) {
    uint32_t r;
    asm("cvt.rna.tf32.f32 %0, %1;" : "=r"(r) : "f"(v));
    return r;
}
__device__ __forceinline__ void mma_tf32(float* d, const uint32_t* a, const uint32_t* b) {
    asm volatile(
        "mma.sync.aligned.m16n8k8.row.col.f32.tf32.tf32.f32 "
        "{%0,%1,%2,%3}, {%4,%5,%6,%7}, {%8,%9}, {%0,%1,%2,%3};"
        : "+f"(d[0]), "+f"(d[1]), "+f"(d[2]), "+f"(d[3])
        : "r"(a[0]), "r"(a[1]), "r"(a[2]), "r"(a[3]), "r"(b[0]), "r"(b[1]));
}
__device__ __forceinline__ uint32_t smem_u32(const void* p) {
    uint32_t a;
    asm("{ .reg .u64 t; cvta.to.shared.u64 t, %1; cvt.u32.u64 %0, t; }" : "=r"(a) : "l"(p));
    return a;
}
__device__ __forceinline__ void cpasync16(uint32_t dst, const void* src) {
    asm volatile("cp.async.cg.shared.global [%0], [%1], 16;" :: "r"(dst), "l"(src) : "memory");
}
#define CP_COMMIT() asm volatile("cp.async.commit_group;" ::: "memory")
#define CP_WAIT(n)  asm volatile("cp.async.wait_group %0;" :: "n"(n) : "memory")

// ---------------- routing kernels -------------------------------------------
__global__ void reset_kernel() {
    int t = threadIdx.x;
    if (t < NEXP) { g_cnt[t] = 0; g_fill[t] = 0; }
}

__global__ void gating_kernel(const float* __restrict__ x,
                              const float* __restrict__ gw,
                              const float* __restrict__ gb,
                              float* __restrict__ out_logits) {
    const int n = blockIdx.x;
    const float* xr = x + (size_t)n * DIM;
    float acc[NEXP];
#pragma unroll
    for (int e = 0; e < NEXP; e++) acc[e] = 0.f;
    for (int d = threadIdx.x; d < DIM; d += blockDim.x) {
        float xv = xr[d];
        const float* g = gw + (size_t)d * NEXP;
#pragma unroll
        for (int e = 0; e < NEXP; e++) acc[e] = fmaf(xv, g[e], acc[e]);
    }
    __shared__ float red[256][NEXP];
#pragma unroll
    for (int e = 0; e < NEXP; e++) red[threadIdx.x][e] = acc[e];
    __syncthreads();
    for (int s = 128; s > 0; s >>= 1) {
        if (threadIdx.x < s)
#pragma unroll
            for (int e = 0; e < NEXP; e++) red[threadIdx.x][e] += red[threadIdx.x + s][e];
        __syncthreads();
    }
    if (threadIdx.x == 0) {
        float l[NEXP];
#pragma unroll
        for (int e = 0; e < NEXP; e++) {
            l[e] = red[0][e] + gb[e];
            out_logits[(size_t)n * NEXP + e] = l[e];
        }
        int i0 = 0;
#pragma unroll
        for (int e = 1; e < NEXP; e++) if (l[e] > l[i0]) i0 = e;
        int i1 = -1;
#pragma unroll
        for (int e = 0; e < NEXP; e++)
            if (e != i0 && (i1 < 0 || l[e] > l[i1])) i1 = e;
        float ex = __expf(l[i1] - l[i0]);
        float w0 = 1.f / (1.f + ex);
        float w1 = ex / (1.f + ex);
        g_texp[n * 2 + 0] = i0; g_twt[n * 2 + 0] = w0;
        g_texp[n * 2 + 1] = i1; g_twt[n * 2 + 1] = w1;
        atomicAdd(&g_cnt[i0], 1);
        atomicAdd(&g_cnt[i1], 1);
    }
}

__global__ void offsets_kernel() {
    if (threadIdx.x == 0) {
        int s = 0;
        for (int e = 0; e < NEXP; e++) { g_off[e] = s; s += g_cnt[e]; }
    }
}

__global__ void fill_kernel() {
    int n = blockIdx.x * blockDim.x + threadIdx.x;
    if (n >= NTOK) return;
#pragma unroll
    for (int s = 0; s < TOPK; s++) {
        int e = g_texp[n * 2 + s];
        int pos = atomicAdd(&g_fill[e], 1);
        int row = g_off[e] + pos;
        g_rowtok[row] = n;
        g_rowwt[row]  = g_twt[n * 2 + s];
        g_tokrow[n * 2 + s] = row;
    }
}

// gather + gate-weight + tf32 round: xg[row] = rna(x[tok] * wt)
__global__ void gather_kernel(const float* __restrict__ x) {
    int row = blockIdx.x;
    int tok = g_rowtok[row];
    float wt = g_rowwt[row];
    const float4* xp = (const float4*)(x + (size_t)tok * DIM);
    float4* gp = (float4*)(g_xg + (size_t)row * DIM);
    float4 v = xp[threadIdx.x];
    v.x = __uint_as_float(f2tf(v.x * wt));
    v.y = __uint_as_float(f2tf(v.y * wt));
    v.z = __uint_as_float(f2tf(v.z * wt));
    v.w = __uint_as_float(f2tf(v.w * wt));
    gp[threadIdx.x] = v;
}

// ---------------- tf32 mma.sync grouped GEMM --------------------------------
// CTA tile 128(M) x 256(N) x 32(K); 8 warps (2M x 4N), warp tile 64x64.
// 4-stage cp.async ring, prefetch distance 3, ONE barrier per chunk.
// A is pre-rounded tf32 bits (no cvt in loop); B cvt'd in registers.
// MODE 0: out = rna(gelu(acc + b1)) -> g_hbuf ; MODE 1: out = (acc + b2)*wt -> g_part
#define AP 36                          // A smem pitch (floats), 36 % 32 = 4 -> conflict-free
#define BPITCH 264                     // B smem pitch (floats), 264 % 32 = 8 -> conflict-free
#define ABYTES (128 * AP * 4)          // 18432
#define BBYTES (32 * BPITCH * 4)       // 33792
#define STAGE_B (ABYTES + BBYTES)      // 52224
#define NSTAGE 4
#define GEMM_SMEM (NSTAGE * STAGE_B)   // 208896

template <int KD, int NB, int MODE>
__global__ __launch_bounds__(256)
void gemm_tc(const float* __restrict__ Abase,
             const float* __restrict__ W,
             const float* __restrict__ bias) {
    const int e   = blockIdx.z;
    const int cnt = g_cnt[e];
    const int m0  = blockIdx.y * 128;
    if (m0 >= cnt) return;
    const int n0   = blockIdx.x * 256;
    const int base = g_off[e];
    constexpr int NC = KD / 32;

    extern __shared__ char smem[];
    const uint32_t sb = smem_u32(smem);
    const int tid  = threadIdx.x;
    const int wid  = tid >> 5;
    const int lane = tid & 31;

    const float* Wg = W + (size_t)e * KD * NB;
    const float* Ag = Abase + (size_t)(base + m0) * KD;

    // cp.async coordinates
    const int arow = tid >> 3, acol = (tid & 7) * 4;    // A: 32 rows/wave, 4 waves
    const int brow = tid >> 6, bcol = (tid & 63) * 4;   // B: 4 rows/wave, 8 waves

    auto load_chunk = [&](int c, int st) {
        const uint32_t sa = sb + st * STAGE_B;
#pragma unroll
        for (int w = 0; w < 4; w++) {
            int r = arow + w * 32;
            cpasync16(sa + (r * AP + acol) * 4, Ag + (size_t)r * KD + c * 32 + acol);
        }
        const uint32_t sB = sa + ABYTES;
#pragma unroll
        for (int w = 0; w < 8; w++) {
            int r = brow + w * 4;
            cpasync16(sB + (r * BPITCH + bcol) * 4, Wg + (size_t)(c * 32 + r) * NB + n0 + bcol);
        }
        CP_COMMIT();
    };

    float acc[4][8][4];
#pragma unroll
    for (int i = 0; i < 4; i++)
#pragma unroll
        for (int j = 0; j < 8; j++)
#pragma unroll
            for (int k = 0; k < 4; k++) acc[i][j][k] = 0.f;

    const int mbase = (wid & 1) * 64;
    const int nbase = (wid >> 1) * 64;
    const int ra = lane >> 2, ca = lane & 3;

    load_chunk(0, 0);
    load_chunk(1, 1);
    load_chunk(2, 2);

    for (int c = 0; c < NC; c++) {
        CP_WAIT(2);
        __syncthreads();
        if (c + 3 < NC) load_chunk(c + 3, (c + 3) & 3);
        else CP_COMMIT();

        const uint32_t* As = (const uint32_t*)(smem + (c & 3) * STAGE_B);
        const float*    Bs = (const float*)(smem + (c & 3) * STAGE_B + ABYTES);

#pragma unroll
        for (int kk = 0; kk < 4; kk++) {
            uint32_t a[4][4], b[8][2];
#pragma unroll
            for (int mt = 0; mt < 4; mt++) {
                const uint32_t* ap = As + (mbase + mt * 16 + ra) * AP + kk * 8 + ca;
                a[mt][0] = ap[0];
                a[mt][1] = ap[8 * AP];
                a[mt][2] = ap[4];
                a[mt][3] = ap[8 * AP + 4];
            }
#pragma unroll
            for (int nt = 0; nt < 8; nt++) {
                const float* bp = Bs + (kk * 8 + ca) * BPITCH + nbase + nt * 8 + ra;
                b[nt][0] = f2tf(bp[0]);
                b[nt][1] = f2tf(bp[4 * BPITCH]);
            }
#pragma unroll
            for (int mt = 0; mt < 4; mt++)
#pragma unroll
                for (int nt = 0; nt < 8; nt++)
                    mma_tf32(acc[mt][nt], a[mt], b[nt]);
        }
    }

    // epilogue
    const float* bp = bias + (size_t)e * NB + n0;
    float* Obase = (MODE == 0 ? g_hbuf : g_part);
#pragma unroll
    for (int mt = 0; mt < 4; mt++) {
#pragma unroll
        for (int half = 0; half < 2; half++) {
            int r = m0 + mbase + mt * 16 + ra + half * 8;
            if (r < cnt) {
                float wt = (MODE == 1) ? g_rowwt[base + r] : 0.f;
                float* op = Obase + (size_t)(base + r) * NB + n0;
#pragma unroll
                for (int nt = 0; nt < 8; nt++) {
                    int col = nbase + nt * 8 + ca * 2;
                    float v0 = acc[mt][nt][half * 2 + 0] + bp[col];
                    float v1 = acc[mt][nt][half * 2 + 1] + bp[col + 1];
                    float2 v;
                    if (MODE == 0) {
                        v0 = 0.5f * v0 * (1.f + erff(v0 * 0.70710678118654752f));
                        v1 = 0.5f * v1 * (1.f + erff(v1 * 0.70710678118654752f));
                        v.x = __uint_as_float(f2tf(v0));
                        v.y = __uint_as_float(f2tf(v1));
                    } else {
                        v.x = v0 * wt;
                        v.y = v1 * wt;
                    }
                    *(float2*)(op + col) = v;
                }
            }
        }
    }
}

// ---------------- combine ----------------------------------------------------
__global__ void combine_kernel(float* __restrict__ out) {
    int idx = blockIdx.x * blockDim.x + threadIdx.x;
    int n  = idx >> 8;
    int d4 = (idx & 255) * 4;
    int r0 = g_tokrow[n * 2 + 0];
    int r1 = g_tokrow[n * 2 + 1];
    float4 p = *(const float4*)(g_part + (size_t)r0 * DIM + d4);
    float4 q = *(const float4*)(g_part + (size_t)r1 * DIM + d4);
    *(float4*)(out + (size_t)n * DIM + d4) =
        make_float4(p.x + q.x, p.y + q.y, p.z + q.z, p.w + q.w);
}

// ---------------- host -------------------------------------------------------
extern "C" void kernel_launch(void* const* d_in, const int* in_sizes, int n_in,
                              void* d_out, int out_size) {
    const float* x  = (const float*)d_in[0];
    const float* gw = (const float*)d_in[1];
    const float* gb = (const float*)d_in[2];
    const float* w1 = (const float*)d_in[3];
    const float* b1 = (const float*)d_in[4];
    const float* w2 = (const float*)d_in[5];
    const float* b2 = (const float*)d_in[6];

    float* out_final  = (float*)d_out;
    float* out_logits = out_final + (size_t)NTOK * DIM;

    void *p_xg, *p_hb;
    cudaGetSymbolAddress(&p_xg, g_xg);
    cudaGetSymbolAddress(&p_hb, g_hbuf);

    cudaFuncSetAttribute(gemm_tc<DIM, HID, 0>, cudaFuncAttributeMaxDynamicSharedMemorySize, GEMM_SMEM);
    cudaFuncSetAttribute(gemm_tc<HID, DIM, 1>, cudaFuncAttributeMaxDynamicSharedMemorySize, GEMM_SMEM);

    reset_kernel<<<1, 32>>>();
    gating_kernel<<<NTOK, 256>>>(x, gw, gb, out_logits);
    offsets_kernel<<<1, 1>>>();
    fill_kernel<<<(NTOK + 255) / 256, 256>>>();
    gather_kernel<<<NASSIGN, 256>>>(x);
    gemm_tc<DIM, HID, 0><<<dim3(HID / 256, NASSIGN / 128, NEXP), 256, GEMM_SMEM>>>(
        (const float*)p_xg, w1, b1);
    gemm_tc<HID, DIM, 1><<<dim3(DIM / 256, NASSIGN / 128, NEXP), 256, GEMM_SMEM>>>(
        (const float*)p_hb, w2, b2);
    combine_kernel<<<(NTOK * DIM / 4) / 256, 256>>>(out_final);
}

// round 9
// speedup vs baseline: 7.2635x; 1.3775x over previous
#include <cuda_runtime.h>
#include <cuda_fp16.h>
#include <cstdint>
#include <math.h>

#define NTOK 4096
#define DIM  1024
#define HID  4096
#define NEXP 8
#define TOPK 2
#define NASSIGN (NTOK * TOPK)        // 8192
#define ROWPAD  (NASSIGN + 128)      // pad rows for ragged M-tiles (zero-init)

// ---------------- scratch (static device globals; no allocations) -----------
__device__ int    g_cnt[NEXP];
__device__ int    g_off[NEXP];
__device__ int    g_fill[NEXP];
__device__ int    g_texp[NASSIGN];
__device__ float  g_twt[NASSIGN];
__device__ int    g_rowtok[NASSIGN];
__device__ float  g_rowwt[NASSIGN];
__device__ int    g_tokrow[NASSIGN];
__device__ __half g_xg  [(size_t)ROWPAD * DIM];     // gathered, weighted x (fp16)
__device__ __half g_hbuf[(size_t)ROWPAD * HID];     // hidden activations (fp16)
__device__ float  g_part[(size_t)NASSIGN * DIM];    // per-assignment outputs
__device__ __half g_w1h [(size_t)NEXP * HID * DIM]; // W1^T fp16: [e][n=H][k=D]
__device__ __half g_w2h [(size_t)NEXP * DIM * HID]; // W2^T fp16: [e][n=D][k=H]

// ---------------- helpers ----------------------------------------------------
__device__ __forceinline__ void mma_f16(float* d, const uint32_t* a, const uint32_t* b) {
    asm volatile(
        "mma.sync.aligned.m16n8k16.row.col.f32.f16.f16.f32 "
        "{%0,%1,%2,%3}, {%4,%5,%6,%7}, {%8,%9}, {%0,%1,%2,%3};"
        : "+f"(d[0]), "+f"(d[1]), "+f"(d[2]), "+f"(d[3])
        : "r"(a[0]), "r"(a[1]), "r"(a[2]), "r"(a[3]), "r"(b[0]), "r"(b[1]));
}
__device__ __forceinline__ uint32_t smem_u32(const void* p) {
    uint32_t a;
    asm("{ .reg .u64 t; cvta.to.shared.u64 t, %1; cvt.u32.u64 %0, t; }" : "=r"(a) : "l"(p));
    return a;
}
__device__ __forceinline__ void cpasync16(uint32_t dst, const void* src) {
    asm volatile("cp.async.cg.shared.global [%0], [%1], 16;" :: "r"(dst), "l"(src) : "memory");
}
#define CP_COMMIT() asm volatile("cp.async.commit_group;" ::: "memory")
#define CP_WAIT(n)  asm volatile("cp.async.wait_group %0;" :: "n"(n) : "memory")

// ---------------- routing kernels -------------------------------------------
__global__ void reset_kernel() {
    int t = threadIdx.x;
    if (t < NEXP) { g_cnt[t] = 0; g_fill[t] = 0; }
}

__global__ void gating_kernel(const float* __restrict__ x,
                              const float* __restrict__ gw,
                              const float* __restrict__ gb,
                              float* __restrict__ out_logits) {
    const int n = blockIdx.x;
    const float* xr = x + (size_t)n * DIM;
    float acc[NEXP];
#pragma unroll
    for (int e = 0; e < NEXP; e++) acc[e] = 0.f;
    for (int d = threadIdx.x; d < DIM; d += blockDim.x) {
        float xv = xr[d];
        const float* g = gw + (size_t)d * NEXP;
#pragma unroll
        for (int e = 0; e < NEXP; e++) acc[e] = fmaf(xv, g[e], acc[e]);
    }
    __shared__ float red[256][NEXP];
#pragma unroll
    for (int e = 0; e < NEXP; e++) red[threadIdx.x][e] = acc[e];
    __syncthreads();
    for (int s = 128; s > 0; s >>= 1) {
        if (threadIdx.x < s)
#pragma unroll
            for (int e = 0; e < NEXP; e++) red[threadIdx.x][e] += red[threadIdx.x + s][e];
        __syncthreads();
    }
    if (threadIdx.x == 0) {
        float l[NEXP];
#pragma unroll
        for (int e = 0; e < NEXP; e++) {
            l[e] = red[0][e] + gb[e];
            out_logits[(size_t)n * NEXP + e] = l[e];
        }
        int i0 = 0;
#pragma unroll
        for (int e = 1; e < NEXP; e++) if (l[e] > l[i0]) i0 = e;
        int i1 = -1;
#pragma unroll
        for (int e = 0; e < NEXP; e++)
            if (e != i0 && (i1 < 0 || l[e] > l[i1])) i1 = e;
        float ex = __expf(l[i1] - l[i0]);
        float w0 = 1.f / (1.f + ex);
        float w1 = ex / (1.f + ex);
        g_texp[n * 2 + 0] = i0; g_twt[n * 2 + 0] = w0;
        g_texp[n * 2 + 1] = i1; g_twt[n * 2 + 1] = w1;
        atomicAdd(&g_cnt[i0], 1);
        atomicAdd(&g_cnt[i1], 1);
    }
}

__global__ void offsets_kernel() {
    if (threadIdx.x == 0) {
        int s = 0;
        for (int e = 0; e < NEXP; e++) { g_off[e] = s; s += g_cnt[e]; }
    }
}

__global__ void fill_kernel() {
    int n = blockIdx.x * blockDim.x + threadIdx.x;
    if (n >= NTOK) return;
#pragma unroll
    for (int s = 0; s < TOPK; s++) {
        int e = g_texp[n * 2 + s];
        int pos = atomicAdd(&g_fill[e], 1);
        int row = g_off[e] + pos;
        g_rowtok[row] = n;
        g_rowwt[row]  = g_twt[n * 2 + s];
        g_tokrow[n * 2 + s] = row;
    }
}

// gather + gate-weight + fp16: xg[row] = h(x[tok] * wt)
__global__ void gather_kernel(const float* __restrict__ x) {
    int row = blockIdx.x;
    int tok = g_rowtok[row];
    float wt = g_rowwt[row];
    const float4* xp = (const float4*)(x + (size_t)tok * DIM);
    float4 v = xp[threadIdx.x];
    __half2 h0 = __floats2half2_rn(v.x * wt, v.y * wt);
    __half2 h1 = __floats2half2_rn(v.z * wt, v.w * wt);
    __half2* gp = (__half2*)(g_xg + (size_t)row * DIM);
    gp[threadIdx.x * 2 + 0] = h0;
    gp[threadIdx.x * 2 + 1] = h1;
}

// transpose + fp16 convert: src[e][R][C] f32 -> dst[e][C][R] fp16
__global__ void transpose_h(const float* __restrict__ src, __half* __restrict__ dst,
                            int R, int C) {
    __shared__ float t[32][33];
    int e = blockIdx.z;
    src += (size_t)e * R * C;
    dst += (size_t)e * R * C;
    int c0 = blockIdx.x * 32, r0 = blockIdx.y * 32;
    int tx = threadIdx.x, ty = threadIdx.y;
#pragma unroll
    for (int j = 0; j < 32; j += 8)
        t[ty + j][tx] = src[(size_t)(r0 + ty + j) * C + c0 + tx];
    __syncthreads();
#pragma unroll
    for (int j = 0; j < 32; j += 8)
        dst[(size_t)(c0 + ty + j) * R + r0 + tx] = __float2half_rn(t[tx][ty + j]);
}

// ---------------- fp16 mma.sync grouped GEMM --------------------------------
// CTA tile 128(M) x 256(N) x 32(K); 8 warps (2M x 4N), warp tile 64x64.
// A [M][K] fp16 K-major; B = pre-transposed weights [N][K] fp16 K-major.
// mma m16n8k16 row.col: both fragments are single u32 LDS, no cvt in loop.
// 4-stage cp.async ring, distance 3, one barrier per chunk.
// MODE 0: out = h(gelu(acc + b1)) -> g_hbuf ; MODE 1: out = (acc + b2)*wt -> g_part
#define APH 40                          // A smem pitch (halves): bank map 20*ra+ca, conflict-free
#define ATILE_B (128 * APH * 2)         // 10240
#define BTILE_B (256 * APH * 2)         // 20480
#define STAGE_B (ATILE_B + BTILE_B)     // 30720
#define GEMM_SMEM (4 * STAGE_B)         // 122880

template <int KD, int NB, int MODE>
__global__ __launch_bounds__(256)
void gemm_tc(const __half* __restrict__ Abase,
             const __half* __restrict__ W,
             const float* __restrict__ bias) {
    const int e   = blockIdx.z;
    const int cnt = g_cnt[e];
    const int m0  = blockIdx.y * 128;
    if (m0 >= cnt) return;
    const int n0   = blockIdx.x * 256;
    const int base = g_off[e];
    constexpr int NC = KD / 32;

    extern __shared__ char smem[];
    const uint32_t sb = smem_u32(smem);
    const int tid  = threadIdx.x;
    const int wid  = tid >> 5;
    const int lane = tid & 31;

    const __half* Wg = W + (size_t)e * (size_t)NB * KD;
    const __half* Ag = Abase + (size_t)(base + m0) * KD;

    auto load_chunk = [&](int c, int st) {
        const uint32_t sa = sb + st * STAGE_B;
#pragma unroll
        for (int w = 0; w < 2; w++) {               // A: 128 rows x 64B
            int u = tid + w * 256;
            int r = u >> 2, k8 = (u & 3) * 8;
            cpasync16(sa + r * (APH * 2) + k8 * 2, Ag + (size_t)r * KD + c * 32 + k8);
        }
        const uint32_t sB = sa + ATILE_B;
#pragma unroll
        for (int w = 0; w < 4; w++) {               // B: 256 rows x 64B
            int u = tid + w * 256;
            int r = u >> 2, k8 = (u & 3) * 8;
            cpasync16(sB + r * (APH * 2) + k8 * 2, Wg + (size_t)(n0 + r) * KD + c * 32 + k8);
        }
        CP_COMMIT();
    };

    float acc[4][8][4];
#pragma unroll
    for (int i = 0; i < 4; i++)
#pragma unroll
        for (int j = 0; j < 8; j++)
#pragma unroll
            for (int k = 0; k < 4; k++) acc[i][j][k] = 0.f;

    const int mbase = (wid & 1) * 64;
    const int nbase = (wid >> 1) * 64;
    const int ra = lane >> 2, ca = lane & 3;

    load_chunk(0, 0);
    load_chunk(1, 1);
    load_chunk(2, 2);

    for (int c = 0; c < NC; c++) {
        CP_WAIT(2);
        __syncthreads();
        if (c + 3 < NC) load_chunk(c + 3, (c + 3) & 3);
        else CP_COMMIT();

        const uint32_t* As32 = (const uint32_t*)(smem + (c & 3) * STAGE_B);
        const uint32_t* Bs32 = (const uint32_t*)(smem + (c & 3) * STAGE_B + ATILE_B);

#pragma unroll
        for (int kk = 0; kk < 2; kk++) {            // two k16 steps per K32 chunk
            uint32_t a[4][4], b[8][2];
#pragma unroll
            for (int mt = 0; mt < 4; mt++) {
                const uint32_t* ap = As32 + (mbase + mt * 16 + ra) * (APH / 2) + kk * 8 + ca;
                a[mt][0] = ap[0];                   // A[g][2ca..]
                a[mt][1] = ap[8 * (APH / 2)];       // A[g+8][2ca..]
                a[mt][2] = ap[4];                   // A[g][2ca+8..]
                a[mt][3] = ap[8 * (APH / 2) + 4];   // A[g+8][2ca+8..]
            }
#pragma unroll
            for (int nt = 0; nt < 8; nt++) {
                const uint32_t* bp = Bs32 + (nbase + nt * 8 + ra) * (APH / 2) + kk * 8 + ca;
                b[nt][0] = bp[0];                   // B^T[n][2ca..]
                b[nt][1] = bp[4];                   // B^T[n][2ca+8..]
            }
#pragma unroll
            for (int mt = 0; mt < 4; mt++)
#pragma unroll
                for (int nt = 0; nt < 8; nt++)
                    mma_f16(acc[mt][nt], a[mt], b[nt]);
        }
    }

    // epilogue
    const float* bp = bias + (size_t)e * NB + n0;
#pragma unroll
    for (int mt = 0; mt < 4; mt++) {
#pragma unroll
        for (int half = 0; half < 2; half++) {
            int r = m0 + mbase + mt * 16 + ra + half * 8;
            if (r < cnt) {
                float wt = (MODE == 1) ? g_rowwt[base + r] : 0.f;
#pragma unroll
                for (int nt = 0; nt < 8; nt++) {
                    int col = nbase + nt * 8 + ca * 2;
                    float v0 = acc[mt][nt][half * 2 + 0] + bp[col];
                    float v1 = acc[mt][nt][half * 2 + 1] + bp[col + 1];
                    if (MODE == 0) {
                        v0 = 0.5f * v0 * (1.f + erff(v0 * 0.70710678118654752f));
                        v1 = 0.5f * v1 * (1.f + erff(v1 * 0.70710678118654752f));
                        *(__half2*)(g_hbuf + (size_t)(base + r) * HID + n0 + col) =
                            __floats2half2_rn(v0, v1);
                    } else {
                        *(float2*)(g_part + (size_t)(base + r) * DIM + n0 + col) =
                            make_float2(v0 * wt, v1 * wt);
                    }
                }
            }
        }
    }
}

// ---------------- combine ----------------------------------------------------
__global__ void combine_kernel(float* __restrict__ out) {
    int idx = blockIdx.x * blockDim.x + threadIdx.x;
    int n  = idx >> 8;
    int d4 = (idx & 255) * 4;
    int r0 = g_tokrow[n * 2 + 0];
    int r1 = g_tokrow[n * 2 + 1];
    float4 p = *(const float4*)(g_part + (size_t)r0 * DIM + d4);
    float4 q = *(const float4*)(g_part + (size_t)r1 * DIM + d4);
    *(float4*)(out + (size_t)n * DIM + d4) =
        make_float4(p.x + q.x, p.y + q.y, p.z + q.z, p.w + q.w);
}

// ---------------- host -------------------------------------------------------
extern "C" void kernel_launch(void* const* d_in, const int* in_sizes, int n_in,
                              void* d_out, int out_size) {
    const float* x  = (const float*)d_in[0];
    const float* gw = (const float*)d_in[1];
    const float* gb = (const float*)d_in[2];
    const float* w1 = (const float*)d_in[3];
    const float* b1 = (const float*)d_in[4];
    const float* w2 = (const float*)d_in[5];
    const float* b2 = (const float*)d_in[6];

    float* out_final  = (float*)d_out;
    float* out_logits = out_final + (size_t)NTOK * DIM;

    void *p_xg, *p_hb, *p_w1h, *p_w2h;
    cudaGetSymbolAddress(&p_xg,  g_xg);
    cudaGetSymbolAddress(&p_hb,  g_hbuf);
    cudaGetSymbolAddress(&p_w1h, g_w1h);
    cudaGetSymbolAddress(&p_w2h, g_w2h);

    cudaFuncSetAttribute(gemm_tc<DIM, HID, 0>, cudaFuncAttributeMaxDynamicSharedMemorySize, GEMM_SMEM);
    cudaFuncSetAttribute(gemm_tc<HID, DIM, 1>, cudaFuncAttributeMaxDynamicSharedMemorySize, GEMM_SMEM);

    reset_kernel<<<1, 32>>>();
    gating_kernel<<<NTOK, 256>>>(x, gw, gb, out_logits);
    offsets_kernel<<<1, 1>>>();
    fill_kernel<<<(NTOK + 255) / 256, 256>>>();
    gather_kernel<<<NASSIGN, 256>>>(x);
    dim3 tb(32, 8);
    transpose_h<<<dim3(HID / 32, DIM / 32, NEXP), tb>>>(w1, (__half*)p_w1h, DIM, HID);
    transpose_h<<<dim3(DIM / 32, HID / 32, NEXP), tb>>>(w2, (__half*)p_w2h, HID, DIM);
    gemm_tc<DIM, HID, 0><<<dim3(HID / 256, NASSIGN / 128, NEXP), 256, GEMM_SMEM>>>(
        (const __half*)p_xg, (const __half*)p_w1h, b1);
    gemm_tc<HID, DIM, 1><<<dim3(DIM / 256, NASSIGN / 128, NEXP), 256, GEMM_SMEM>>>(
        (const __half*)p_hb, (const __half*)p_w2h, b2);
    combine_kernel<<<(NTOK * DIM / 4) / 256, 256>>>(out_final);
}

// round 10
// speedup vs baseline: 7.5299x; 1.0367x over previous
#include <cuda_runtime.h>
#include <cuda_fp16.h>
#include <cstdint>
#include <math.h>

#define NTOK 4096
#define DIM  1024
#define HID  4096
#define NEXP 8
#define TOPK 2
#define NASSIGN (NTOK * TOPK)        // 8192
#define ROWPAD  (NASSIGN + 128)      // pad rows for ragged M-tiles (zero-init)

// ---------------- scratch (static device globals; no allocations) -----------
__device__ int    g_cnt[NEXP];
__device__ int    g_off[NEXP];
__device__ int    g_fill[NEXP];
__device__ int    g_texp[NASSIGN];
__device__ float  g_twt[NASSIGN];
__device__ int    g_rowtok[NASSIGN];
__device__ float  g_rowwt[NASSIGN];
__device__ int    g_tokrow[NASSIGN];
__device__ __half g_xg  [(size_t)ROWPAD * DIM];     // gathered, weighted x (fp16)
__device__ __half g_hbuf[(size_t)ROWPAD * HID];     // hidden activations (fp16)
__device__ float  g_part[(size_t)NASSIGN * DIM];    // per-assignment outputs
__device__ __half g_w1h [(size_t)NEXP * HID * DIM]; // W1^T fp16: [e][n=H][k=D]
__device__ __half g_w2h [(size_t)NEXP * DIM * HID]; // W2^T fp16: [e][n=D][k=H]

// ---------------- helpers ----------------------------------------------------
__device__ __forceinline__ void mma_f16(float* d, const uint32_t* a, const uint32_t* b) {
    asm volatile(
        "mma.sync.aligned.m16n8k16.row.col.f32.f16.f16.f32 "
        "{%0,%1,%2,%3}, {%4,%5,%6,%7}, {%8,%9}, {%0,%1,%2,%3};"
        : "+f"(d[0]), "+f"(d[1]), "+f"(d[2]), "+f"(d[3])
        : "r"(a[0]), "r"(a[1]), "r"(a[2]), "r"(a[3]), "r"(b[0]), "r"(b[1]));
}
__device__ __forceinline__ uint32_t smem_u32(const void* p) {
    uint32_t a;
    asm("{ .reg .u64 t; cvta.to.shared.u64 t, %1; cvt.u32.u64 %0, t; }" : "=r"(a) : "l"(p));
    return a;
}
__device__ __forceinline__ void cpasync16(uint32_t dst, const void* src) {
    asm volatile("cp.async.cg.shared.global [%0], [%1], 16;" :: "r"(dst), "l"(src) : "memory");
}
#define CP_COMMIT() asm volatile("cp.async.commit_group;" ::: "memory")
#define CP_WAIT(n)  asm volatile("cp.async.wait_group %0;" :: "n"(n) : "memory")

// ---------------- routing kernels -------------------------------------------
__global__ void reset_kernel() {
    int t = threadIdx.x;
    if (t < NEXP) { g_cnt[t] = 0; g_fill[t] = 0; }
}

__global__ void gating_kernel(const float* __restrict__ x,
                              const float* __restrict__ gw,
                              const float* __restrict__ gb,
                              float* __restrict__ out_logits) {
    const int n = blockIdx.x;
    const float* xr = x + (size_t)n * DIM;
    float acc[NEXP];
#pragma unroll
    for (int e = 0; e < NEXP; e++) acc[e] = 0.f;
    for (int d = threadIdx.x; d < DIM; d += blockDim.x) {
        float xv = xr[d];
        const float* g = gw + (size_t)d * NEXP;
#pragma unroll
        for (int e = 0; e < NEXP; e++) acc[e] = fmaf(xv, g[e], acc[e]);
    }
    __shared__ float red[256][NEXP];
#pragma unroll
    for (int e = 0; e < NEXP; e++) red[threadIdx.x][e] = acc[e];
    __syncthreads();
    for (int s = 128; s > 0; s >>= 1) {
        if (threadIdx.x < s)
#pragma unroll
            for (int e = 0; e < NEXP; e++) red[threadIdx.x][e] += red[threadIdx.x + s][e];
        __syncthreads();
    }
    if (threadIdx.x == 0) {
        float l[NEXP];
#pragma unroll
        for (int e = 0; e < NEXP; e++) {
            l[e] = red[0][e] + gb[e];
            out_logits[(size_t)n * NEXP + e] = l[e];
        }
        int i0 = 0;
#pragma unroll
        for (int e = 1; e < NEXP; e++) if (l[e] > l[i0]) i0 = e;
        int i1 = -1;
#pragma unroll
        for (int e = 0; e < NEXP; e++)
            if (e != i0 && (i1 < 0 || l[e] > l[i1])) i1 = e;
        float ex = __expf(l[i1] - l[i0]);
        float w0 = 1.f / (1.f + ex);
        float w1 = ex / (1.f + ex);
        g_texp[n * 2 + 0] = i0; g_twt[n * 2 + 0] = w0;
        g_texp[n * 2 + 1] = i1; g_twt[n * 2 + 1] = w1;
        atomicAdd(&g_cnt[i0], 1);
        atomicAdd(&g_cnt[i1], 1);
    }
}

__global__ void offsets_kernel() {
    if (threadIdx.x == 0) {
        int s = 0;
        for (int e = 0; e < NEXP; e++) { g_off[e] = s; s += g_cnt[e]; }
    }
}

__global__ void fill_kernel() {
    int n = blockIdx.x * blockDim.x + threadIdx.x;
    if (n >= NTOK) return;
#pragma unroll
    for (int s = 0; s < TOPK; s++) {
        int e = g_texp[n * 2 + s];
        int pos = atomicAdd(&g_fill[e], 1);
        int row = g_off[e] + pos;
        g_rowtok[row] = n;
        g_rowwt[row]  = g_twt[n * 2 + s];
        g_tokrow[n * 2 + s] = row;
    }
}

// gather + gate-weight + fp16: xg[row] = h(x[tok] * wt)
__global__ void gather_kernel(const float* __restrict__ x) {
    int row = blockIdx.x;
    int tok = g_rowtok[row];
    float wt = g_rowwt[row];
    const float4* xp = (const float4*)(x + (size_t)tok * DIM);
    float4 v = xp[threadIdx.x];
    __half2 h0 = __floats2half2_rn(v.x * wt, v.y * wt);
    __half2 h1 = __floats2half2_rn(v.z * wt, v.w * wt);
    __half2* gp = (__half2*)(g_xg + (size_t)row * DIM);
    gp[threadIdx.x * 2 + 0] = h0;
    gp[threadIdx.x * 2 + 1] = h1;
}

// fast cast+transpose: src[e][R][C] f32 -> dst[e][C][R] fp16
// 64x64 tile, 256 threads; float4 coalesced reads, uint2 (half4) coalesced writes.
__global__ void castT_kernel(const float* __restrict__ src, __half* __restrict__ dst,
                             int R, int C) {
    __shared__ __half s[64][66];
    const int e = blockIdx.z;
    src += (size_t)e * R * C;
    dst += (size_t)e * R * C;
    const int c0 = blockIdx.x * 64, r0 = blockIdx.y * 64;
    const int tid = threadIdx.x;

    const int rr = tid >> 4, cc = (tid & 15) * 4;   // 16 rows x 64 cols per pass
#pragma unroll
    for (int i = 0; i < 4; i++) {
        int r = rr + i * 16;
        float4 v = *(const float4*)(src + (size_t)(r0 + r) * C + c0 + cc);
        s[cc + 0][r] = __float2half_rn(v.x);
        s[cc + 1][r] = __float2half_rn(v.y);
        s[cc + 2][r] = __float2half_rn(v.z);
        s[cc + 3][r] = __float2half_rn(v.w);
    }
    __syncthreads();

    const int co = tid >> 4, ro = (tid & 15) * 4;   // 16 cols x 64 rows per pass
#pragma unroll
    for (int i = 0; i < 4; i++) {
        int c = co + i * 16;
        __half2 a = *(__half2*)&s[c][ro];
        __half2 b = *(__half2*)&s[c][ro + 2];
        uint2 u;
        u.x = *(uint32_t*)&a;
        u.y = *(uint32_t*)&b;
        *(uint2*)(dst + (size_t)(c0 + c) * R + r0 + ro) = u;
    }
}

// ---------------- fp16 mma.sync grouped GEMM --------------------------------
// CTA tile 128(M) x NTILE(N) x 32(K); 8 warps (2M x 4N), warp tile 64 x NTILE/4.
// A [M][K] fp16 K-major; B = pre-transposed weights [N][K] fp16 K-major.
// 4-stage cp.async ring, distance 3, one barrier per chunk.
// MODE 0: out = h(gelu(acc + b1)) -> g_hbuf ; MODE 1: out = (acc + b2)*wt -> g_part
#define APH 40                                   // smem pitch (halves), conflict-free

template <int KD, int NB, int NTILE, int MODE, int OCC>
__global__ __launch_bounds__(256, OCC)
void gemm_tc(const __half* __restrict__ Abase,
             const __half* __restrict__ W,
             const float* __restrict__ bias) {
    constexpr int ATILE_B = 128 * APH * 2;
    constexpr int BTILE_B = NTILE * APH * 2;
    constexpr int STAGE_B = ATILE_B + BTILE_B;
    constexpr int NT = NTILE / 32;               // nt count per warp (8 or 4)
    constexpr int NC = KD / 32;

    const int e   = blockIdx.z;
    const int cnt = g_cnt[e];
    const int m0  = blockIdx.y * 128;
    if (m0 >= cnt) return;
    const int n0   = blockIdx.x * NTILE;
    const int base = g_off[e];

    extern __shared__ char smem[];
    const uint32_t sb = smem_u32(smem);
    const int tid  = threadIdx.x;
    const int wid  = tid >> 5;
    const int lane = tid & 31;

    const __half* Wg = W + (size_t)e * (size_t)NB * KD;
    const __half* Ag = Abase + (size_t)(base + m0) * KD;

    auto load_chunk = [&](int c, int st) {
        const uint32_t sa = sb + st * STAGE_B;
#pragma unroll
        for (int w = 0; w < 2; w++) {            // A: 128 rows x 64B
            int u = tid + w * 256;
            int r = u >> 2, k8 = (u & 3) * 8;
            cpasync16(sa + r * (APH * 2) + k8 * 2, Ag + (size_t)r * KD + c * 32 + k8);
        }
        const uint32_t sB = sa + ATILE_B;
#pragma unroll
        for (int w = 0; w < NTILE / 64; w++) {   // B: NTILE rows x 64B
            int u = tid + w * 256;
            int r = u >> 2, k8 = (u & 3) * 8;
            cpasync16(sB + r * (APH * 2) + k8 * 2, Wg + (size_t)(n0 + r) * KD + c * 32 + k8);
        }
        CP_COMMIT();
    };

    float acc[4][NT][4];
#pragma unroll
    for (int i = 0; i < 4; i++)
#pragma unroll
        for (int j = 0; j < NT; j++)
#pragma unroll
            for (int k = 0; k < 4; k++) acc[i][j][k] = 0.f;

    const int mbase = (wid & 1) * 64;
    const int nbase = (wid >> 1) * (NTILE / 4);
    const int ra = lane >> 2, ca = lane & 3;

    load_chunk(0, 0);
    load_chunk(1, 1);
    load_chunk(2, 2);

    for (int c = 0; c < NC; c++) {
        CP_WAIT(2);
        __syncthreads();
        if (c + 3 < NC) load_chunk(c + 3, (c + 3) & 3);
        else CP_COMMIT();

        const uint32_t* As32 = (const uint32_t*)(smem + (c & 3) * STAGE_B);
        const uint32_t* Bs32 = (const uint32_t*)(smem + (c & 3) * STAGE_B + ATILE_B);

#pragma unroll
        for (int kk = 0; kk < 2; kk++) {         // two k16 steps per K32 chunk
            uint32_t a[4][4], b[NT][2];
#pragma unroll
            for (int mt = 0; mt < 4; mt++) {
                const uint32_t* ap = As32 + (mbase + mt * 16 + ra) * (APH / 2) + kk * 8 + ca;
                a[mt][0] = ap[0];
                a[mt][1] = ap[8 * (APH / 2)];
                a[mt][2] = ap[4];
                a[mt][3] = ap[8 * (APH / 2) + 4];
            }
#pragma unroll
            for (int nt = 0; nt < NT; nt++) {
                const uint32_t* bp = Bs32 + (nbase + nt * 8 + ra) * (APH / 2) + kk * 8 + ca;
                b[nt][0] = bp[0];
                b[nt][1] = bp[4];
            }
#pragma unroll
            for (int mt = 0; mt < 4; mt++)
#pragma unroll
                for (int nt = 0; nt < NT; nt++)
                    mma_f16(acc[mt][nt], a[mt], b[nt]);
        }
    }

    // epilogue
    const float* bp = bias + (size_t)e * NB + n0;
#pragma unroll
    for (int mt = 0; mt < 4; mt++) {
#pragma unroll
        for (int half = 0; half < 2; half++) {
            int r = m0 + mbase + mt * 16 + ra + half * 8;
            if (r < cnt) {
                float wt = (MODE == 1) ? g_rowwt[base + r] : 0.f;
#pragma unroll
                for (int nt = 0; nt < NT; nt++) {
                    int col = nbase + nt * 8 + ca * 2;
                    float v0 = acc[mt][nt][half * 2 + 0] + bp[col];
                    float v1 = acc[mt][nt][half * 2 + 1] + bp[col + 1];
                    if (MODE == 0) {
                        v0 = 0.5f * v0 * (1.f + erff(v0 * 0.70710678118654752f));
                        v1 = 0.5f * v1 * (1.f + erff(v1 * 0.70710678118654752f));
                        *(__half2*)(g_hbuf + (size_t)(base + r) * HID + n0 + col) =
                            __floats2half2_rn(v0, v1);
                    } else {
                        *(float2*)(g_part + (size_t)(base + r) * DIM + n0 + col) =
                            make_float2(v0 * wt, v1 * wt);
                    }
                }
            }
        }
    }
}

// ---------------- combine ----------------------------------------------------
__global__ void combine_kernel(float* __restrict__ out) {
    int idx = blockIdx.x * blockDim.x + threadIdx.x;
    int n  = idx >> 8;
    int d4 = (idx & 255) * 4;
    int r0 = g_tokrow[n * 2 + 0];
    int r1 = g_tokrow[n * 2 + 1];
    float4 p = *(const float4*)(g_part + (size_t)r0 * DIM + d4);
    float4 q = *(const float4*)(g_part + (size_t)r1 * DIM + d4);
    *(float4*)(out + (size_t)n * DIM + d4) =
        make_float4(p.x + q.x, p.y + q.y, p.z + q.z, p.w + q.w);
}

// ---------------- host -------------------------------------------------------
extern "C" void kernel_launch(void* const* d_in, const int* in_sizes, int n_in,
                              void* d_out, int out_size) {
    const float* x  = (const float*)d_in[0];
    const float* gw = (const float*)d_in[1];
    const float* gb = (const float*)d_in[2];
    const float* w1 = (const float*)d_in[3];
    const float* b1 = (const float*)d_in[4];
    const float* w2 = (const float*)d_in[5];
    const float* b2 = (const float*)d_in[6];

    float* out_final  = (float*)d_out;
    float* out_logits = out_final + (size_t)NTOK * DIM;

    void *p_xg, *p_hb, *p_w1h, *p_w2h;
    cudaGetSymbolAddress(&p_xg,  g_xg);
    cudaGetSymbolAddress(&p_hb,  g_hbuf);
    cudaGetSymbolAddress(&p_w1h, g_w1h);
    cudaGetSymbolAddress(&p_w2h, g_w2h);

    constexpr int SMEM1 = 4 * (128 + 256) * APH * 2;   // 122880
    constexpr int SMEM2 = 4 * (128 + 128) * APH * 2;   // 81920
    cudaFuncSetAttribute(gemm_tc<DIM, HID, 256, 0, 1>,
                         cudaFuncAttributeMaxDynamicSharedMemorySize, SMEM1);
    cudaFuncSetAttribute(gemm_tc<HID, DIM, 128, 1, 2>,
                         cudaFuncAttributeMaxDynamicSharedMemorySize, SMEM2);

    reset_kernel<<<1, 32>>>();
    gating_kernel<<<NTOK, 256>>>(x, gw, gb, out_logits);
    offsets_kernel<<<1, 1>>>();
    fill_kernel<<<(NTOK + 255) / 256, 256>>>();
    gather_kernel<<<NASSIGN, 256>>>(x);
    castT_kernel<<<dim3(HID / 64, DIM / 64, NEXP), 256>>>(w1, (__half*)p_w1h, DIM, HID);
    castT_kernel<<<dim3(DIM / 64, HID / 64, NEXP), 256>>>(w2, (__half*)p_w2h, HID, DIM);
    gemm_tc<DIM, HID, 256, 0, 1><<<dim3(HID / 256, NASSIGN / 128, NEXP), 256, SMEM1>>>(
        (const __half*)p_xg, (const __half*)p_w1h, b1);
    gemm_tc<HID, DIM, 128, 1, 2><<<dim3(DIM / 128, NASSIGN / 128, NEXP), 256, SMEM2>>>(
        (const __half*)p_hb, (const __half*)p_w2h, b2);
    combine_kernel<<<(NTOK * DIM / 4) / 256, 256>>>(out_final);
}

// round 14
// speedup vs baseline: 8.0310x; 1.0665x over previous
#include <cuda_runtime.h>
#include <cuda_fp16.h>
#include <cstdint>
#include <math.h>

#define NTOK 4096
#define DIM  1024
#define HID  4096
#define NEXP 8
#define TOPK 2
#define NASSIGN (NTOK * TOPK)        // 8192
#define ROWPAD  (NASSIGN + 128)      // pad rows for ragged M-tiles (zero-init)

// ---------------- scratch (static device globals; no allocations) -----------
__device__ int    g_cnt[NEXP];
__device__ int    g_off[NEXP];
__device__ int    g_fill[NEXP];
__device__ int    g_texp[NASSIGN];
__device__ float  g_twt[NASSIGN];
__device__ int    g_rowtok[NASSIGN];
__device__ float  g_rowwt[NASSIGN];
__device__ int    g_tokrow[NASSIGN];
__device__ __half g_xg  [(size_t)ROWPAD * DIM];     // gathered, weighted x (fp16)
__device__ __half g_hbuf[(size_t)ROWPAD * HID];     // hidden activations (fp16)
__device__ float  g_part[(size_t)NASSIGN * DIM];    // per-assignment outputs
__device__ __half g_w1h [(size_t)NEXP * HID * DIM]; // W1^T fp16: [e][n=H][k=D]
__device__ __half g_w2h [(size_t)NEXP * DIM * HID]; // W2^T fp16: [e][n=D][k=H]

// ---------------- helpers ----------------------------------------------------
__device__ __forceinline__ void mma_f16(float* d, const uint32_t* a, const uint32_t* b) {
    asm volatile(
        "mma.sync.aligned.m16n8k16.row.col.f32.f16.f16.f32 "
        "{%0,%1,%2,%3}, {%4,%5,%6,%7}, {%8,%9}, {%0,%1,%2,%3};"
        : "+f"(d[0]), "+f"(d[1]), "+f"(d[2]), "+f"(d[3])
        : "r"(a[0]), "r"(a[1]), "r"(a[2]), "r"(a[3]), "r"(b[0]), "r"(b[1]));
}
__device__ __forceinline__ void ldsm4(uint32_t* r, uint32_t addr) {
    asm volatile("ldmatrix.sync.aligned.m8n8.x4.shared.b16 {%0,%1,%2,%3}, [%4];"
                 : "=r"(r[0]), "=r"(r[1]), "=r"(r[2]), "=r"(r[3]) : "r"(addr));
}
__device__ __forceinline__ uint32_t smem_u32(const void* p) {
    uint32_t a;
    asm("{ .reg .u64 t; cvta.to.shared.u64 t, %1; cvt.u32.u64 %0, t; }" : "=r"(a) : "l"(p));
    return a;
}
__device__ __forceinline__ void cpasync16(uint32_t dst, const void* src) {
    asm volatile("cp.async.cg.shared.global [%0], [%1], 16;" :: "r"(dst), "l"(src) : "memory");
}
#define CP_COMMIT() asm volatile("cp.async.commit_group;" ::: "memory")
#define CP_WAIT(n)  asm volatile("cp.async.wait_group %0;" :: "n"(n) : "memory")

// ---------------- routing kernels -------------------------------------------
__global__ void reset_kernel() {
    int t = threadIdx.x;
    if (t < NEXP) { g_cnt[t] = 0; g_fill[t] = 0; }
}

__global__ void gating_kernel(const float* __restrict__ x,
                              const float* __restrict__ gw,
                              const float* __restrict__ gb,
                              float* __restrict__ out_logits) {
    const int n = blockIdx.x;
    const float* xr = x + (size_t)n * DIM;
    float acc[NEXP];
#pragma unroll
    for (int e = 0; e < NEXP; e++) acc[e] = 0.f;
    for (int d = threadIdx.x; d < DIM; d += blockDim.x) {
        float xv = xr[d];
        const float* g = gw + (size_t)d * NEXP;
#pragma unroll
        for (int e = 0; e < NEXP; e++) acc[e] = fmaf(xv, g[e], acc[e]);
    }
    __shared__ float red[256][NEXP];
#pragma unroll
    for (int e = 0; e < NEXP; e++) red[threadIdx.x][e] = acc[e];
    __syncthreads();
    for (int s = 128; s > 0; s >>= 1) {
        if (threadIdx.x < s)
#pragma unroll
            for (int e = 0; e < NEXP; e++) red[threadIdx.x][e] += red[threadIdx.x + s][e];
        __syncthreads();
    }
    if (threadIdx.x == 0) {
        float l[NEXP];
#pragma unroll
        for (int e = 0; e < NEXP; e++) {
            l[e] = red[0][e] + gb[e];
            out_logits[(size_t)n * NEXP + e] = l[e];
        }
        int i0 = 0;
#pragma unroll
        for (int e = 1; e < NEXP; e++) if (l[e] > l[i0]) i0 = e;
        int i1 = -1;
#pragma unroll
        for (int e = 0; e < NEXP; e++)
            if (e != i0 && (i1 < 0 || l[e] > l[i1])) i1 = e;
        float ex = __expf(l[i1] - l[i0]);
        float w0 = 1.f / (1.f + ex);
        float w1 = ex / (1.f + ex);
        g_texp[n * 2 + 0] = i0; g_twt[n * 2 + 0] = w0;
        g_texp[n * 2 + 1] = i1; g_twt[n * 2 + 1] = w1;
        atomicAdd(&g_cnt[i0], 1);
        atomicAdd(&g_cnt[i1], 1);
    }
}

__global__ void offsets_kernel() {
    if (threadIdx.x == 0) {
        int s = 0;
        for (int e = 0; e < NEXP; e++) { g_off[e] = s; s += g_cnt[e]; }
    }
}

__global__ void fill_kernel() {
    int n = blockIdx.x * blockDim.x + threadIdx.x;
    if (n >= NTOK) return;
#pragma unroll
    for (int s = 0; s < TOPK; s++) {
        int e = g_texp[n * 2 + s];
        int pos = atomicAdd(&g_fill[e], 1);
        int row = g_off[e] + pos;
        g_rowtok[row] = n;
        g_rowwt[row]  = g_twt[n * 2 + s];
        g_tokrow[n * 2 + s] = row;
    }
}

// gather + gate-weight + fp16: xg[row] = h(x[tok] * wt)
__global__ void gather_kernel(const float* __restrict__ x) {
    int row = blockIdx.x;
    int tok = g_rowtok[row];
    float wt = g_rowwt[row];
    const float4* xp = (const float4*)(x + (size_t)tok * DIM);
    float4 v = xp[threadIdx.x];
    __half2 h0 = __floats2half2_rn(v.x * wt, v.y * wt);
    __half2 h1 = __floats2half2_rn(v.z * wt, v.w * wt);
    __half2* gp = (__half2*)(g_xg + (size_t)row * DIM);
    gp[threadIdx.x * 2 + 0] = h0;
    gp[threadIdx.x * 2 + 1] = h1;
}

// fast cast+transpose: src[e][R][C] f32 -> dst[e][C][R] fp16
__global__ void castT_kernel(const float* __restrict__ src, __half* __restrict__ dst,
                             int R, int C) {
    __shared__ __half s[64][66];
    const int e = blockIdx.z;
    src += (size_t)e * R * C;
    dst += (size_t)e * R * C;
    const int c0 = blockIdx.x * 64, r0 = blockIdx.y * 64;
    const int tid = threadIdx.x;

    const int rr = tid >> 4, cc = (tid & 15) * 4;
#pragma unroll
    for (int i = 0; i < 4; i++) {
        int r = rr + i * 16;
        float4 v = *(const float4*)(src + (size_t)(r0 + r) * C + c0 + cc);
        s[cc + 0][r] = __float2half_rn(v.x);
        s[cc + 1][r] = __float2half_rn(v.y);
        s[cc + 2][r] = __float2half_rn(v.z);
        s[cc + 3][r] = __float2half_rn(v.w);
    }
    __syncthreads();

    const int co = tid >> 4, ro = (tid & 15) * 4;
#pragma unroll
    for (int i = 0; i < 4; i++) {
        int c = co + i * 16;
        __half2 a = *(__half2*)&s[c][ro];
        __half2 b = *(__half2*)&s[c][ro + 2];
        uint2 u;
        u.x = *(uint32_t*)&a;
        u.y = *(uint32_t*)&b;
        *(uint2*)(dst + (size_t)(c0 + c) * R + r0 + ro) = u;
    }
}

// ---------------- fp16 mma.sync grouped GEMM (ldmatrix fragments) ------------
// CTA tile 128(M) x NTILE(N) x 32(K); 8 warps (2M x 4N), warp tile 64 x NTILE/4.
// 4-stage cp.async ring, distance 3, one barrier per chunk.
// MODE 0: out = h(gelu(acc + b1)) -> g_hbuf ; MODE 1: out = (acc + b2)*wt -> g_part
#define APH 40                                   // smem pitch (halves), ldmatrix conflict-free

template <int KD, int NB, int NTILE, int MODE, int OCC>
__global__ __launch_bounds__(256, OCC)
void gemm_tc(const __half* __restrict__ Abase,
             const __half* __restrict__ W,
             const float* __restrict__ bias) {
    constexpr int ATILE_B = 128 * APH * 2;
    constexpr int BTILE_B = NTILE * APH * 2;
    constexpr int STAGE_B = ATILE_B + BTILE_B;
    constexpr int NT = NTILE / 32;               // nt count per warp (8 or 4)
    constexpr int NC = KD / 32;

    const int e   = blockIdx.z;
    const int cnt = g_cnt[e];
    const int m0  = blockIdx.y * 128;
    if (m0 >= cnt) return;
    const int n0   = blockIdx.x * NTILE;
    const int base = g_off[e];

    extern __shared__ char smem[];
    const uint32_t sb = smem_u32(smem);
    const int tid  = threadIdx.x;
    const int wid  = tid >> 5;
    const int lane = tid & 31;

    const __half* Wg = W + (size_t)e * (size_t)NB * KD;
    const __half* Ag = Abase + (size_t)(base + m0) * KD;

    auto load_chunk = [&](int c, int st) {
        const uint32_t sa = sb + st * STAGE_B;
#pragma unroll
        for (int w = 0; w < 2; w++) {            // A: 128 rows x 64B
            int u = tid + w * 256;
            int r = u >> 2, k8 = (u & 3) * 8;
            cpasync16(sa + r * (APH * 2) + k8 * 2, Ag + (size_t)r * KD + c * 32 + k8);
        }
        const uint32_t sB = sa + ATILE_B;
#pragma unroll
        for (int w = 0; w < NTILE / 64; w++) {   // B: NTILE rows x 64B
            int u = tid + w * 256;
            int r = u >> 2, k8 = (u & 3) * 8;
            cpasync16(sB + r * (APH * 2) + k8 * 2, Wg + (size_t)(n0 + r) * KD + c * 32 + k8);
        }
        CP_COMMIT();
    };

    float acc[4][NT][4];
#pragma unroll
    for (int i = 0; i < 4; i++)
#pragma unroll
        for (int j = 0; j < NT; j++)
#pragma unroll
            for (int k = 0; k < 4; k++) acc[i][j][k] = 0.f;

    const int mbase = (wid & 1) * 64;
    const int nbase = (wid >> 1) * (NTILE / 4);

    // ldmatrix lane addressing (see theory):
    const int rA    = lane & 15;                 // A row within 16x16 tile
    const int kofsA = (lane >> 4) * 8;           // A k offset (halves)
    const int rB    = (lane & 7) + (lane >> 4) * 8;   // B n-row within 16-row pair
    const int kofsB = ((lane >> 3) & 1) * 8;     // B k offset (halves)

    // per-thread byte offsets inside a stage
    const uint32_t aOff = (uint32_t)(mbase + rA) * (APH * 2) + kofsA * 2;
    const uint32_t bOff = ATILE_B + (uint32_t)(nbase + rB) * (APH * 2) + kofsB * 2;

    load_chunk(0, 0);
    load_chunk(1, 1);
    load_chunk(2, 2);

    for (int c = 0; c < NC; c++) {
        CP_WAIT(2);
        __syncthreads();
        if (c + 3 < NC) load_chunk(c + 3, (c + 3) & 3);
        else CP_COMMIT();

        const uint32_t st = sb + (c & 3) * STAGE_B;

#pragma unroll
        for (int kk = 0; kk < 2; kk++) {         // two k16 steps per K32 chunk
            uint32_t a[4][4], b[NT][2];
#pragma unroll
            for (int mt = 0; mt < 4; mt++)
                ldsm4(a[mt], st + aOff + mt * (16 * APH * 2) + kk * 32);
#pragma unroll
            for (int np = 0; np < NT / 2; np++) {
                uint32_t r[4];
                ldsm4(r, st + bOff + np * (16 * APH * 2) + kk * 32);
                b[np * 2 + 0][0] = r[0];
                b[np * 2 + 0][1] = r[1];
                b[np * 2 + 1][0] = r[2];
                b[np * 2 + 1][1] = r[3];
            }
#pragma unroll
            for (int mt = 0; mt < 4; mt++)
#pragma unroll
                for (int nt = 0; nt < NT; nt++)
                    mma_f16(acc[mt][nt], a[mt], b[nt]);
        }
    }

    // epilogue
    const float* bp = bias + (size_t)e * NB + n0;
    const int ra = lane >> 2, ca = lane & 3;
#pragma unroll
    for (int mt = 0; mt < 4; mt++) {
#pragma unroll
        for (int half = 0; half < 2; half++) {
            int r = m0 + mbase + mt * 16 + ra + half * 8;
            if (r < cnt) {
                float wt = (MODE == 1) ? g_rowwt[base + r] : 0.f;
#pragma unroll
                for (int nt = 0; nt < NT; nt++) {
                    int col = nbase + nt * 8 + ca * 2;
                    float v0 = acc[mt][nt][half * 2 + 0] + bp[col];
                    float v1 = acc[mt][nt][half * 2 + 1] + bp[col + 1];
                    if (MODE == 0) {
                        v0 = 0.5f * v0 * (1.f + erff(v0 * 0.70710678118654752f));
                        v1 = 0.5f * v1 * (1.f + erff(v1 * 0.70710678118654752f));
                        *(__half2*)(g_hbuf + (size_t)(base + r) * HID + n0 + col) =
                            __floats2half2_rn(v0, v1);
                    } else {
                        *(float2*)(g_part + (size_t)(base + r) * DIM + n0 + col) =
                            make_float2(v0 * wt, v1 * wt);
                    }
                }
            }
        }
    }
}

// ---------------- combine ----------------------------------------------------
__global__ void combine_kernel(float* __restrict__ out) {
    int idx = blockIdx.x * blockDim.x + threadIdx.x;
    int n  = idx >> 8;
    int d4 = (idx & 255) * 4;
    int r0 = g_tokrow[n * 2 + 0];
    int r1 = g_tokrow[n * 2 + 1];
    float4 p = *(const float4*)(g_part + (size_t)r0 * DIM + d4);
    float4 q = *(const float4*)(g_part + (size_t)r1 * DIM + d4);
    *(float4*)(out + (size_t)n * DIM + d4) =
        make_float4(p.x + q.x, p.y + q.y, p.z + q.z, p.w + q.w);
}

// ---------------- host -------------------------------------------------------
extern "C" void kernel_launch(void* const* d_in, const int* in_sizes, int n_in,
                              void* d_out, int out_size) {
    const float* x  = (const float*)d_in[0];
    const float* gw = (const float*)d_in[1];
    const float* gb = (const float*)d_in[2];
    const float* w1 = (const float*)d_in[3];
    const float* b1 = (const float*)d_in[4];
    const float* w2 = (const float*)d_in[5];
    const float* b2 = (const float*)d_in[6];

    float* out_final  = (float*)d_out;
    float* out_logits = out_final + (size_t)NTOK * DIM;

    void *p_xg, *p_hb, *p_w1h, *p_w2h;
    cudaGetSymbolAddress(&p_xg,  g_xg);
    cudaGetSymbolAddress(&p_hb,  g_hbuf);
    cudaGetSymbolAddress(&p_w1h, g_w1h);
    cudaGetSymbolAddress(&p_w2h, g_w2h);

    constexpr int SMEM1 = 4 * (128 + 256) * APH * 2;   // 122880
    constexpr int SMEM2 = 4 * (128 + 128) * APH * 2;   // 81920
    cudaFuncSetAttribute(gemm_tc<DIM, HID, 256, 0, 1>,
                         cudaFuncAttributeMaxDynamicSharedMemorySize, SMEM1);
    cudaFuncSetAttribute(gemm_tc<HID, DIM, 128, 1, 2>,
                         cudaFuncAttributeMaxDynamicSharedMemorySize, SMEM2);

    reset_kernel<<<1, 32>>>();
    gating_kernel<<<NTOK, 256>>>(x, gw, gb, out_logits);
    offsets_kernel<<<1, 1>>>();
    fill_kernel<<<(NTOK + 255) / 256, 256>>>();
    gather_kernel<<<NASSIGN, 256>>>(x);
    castT_kernel<<<dim3(HID / 64, DIM / 64, NEXP), 256>>>(w1, (__half*)p_w1h, DIM, HID);
    castT_kernel<<<dim3(DIM / 64, HID / 64, NEXP), 256>>>(w2, (__half*)p_w2h, HID, DIM);
    gemm_tc<DIM, HID, 256, 0, 1><<<dim3(HID / 256, NASSIGN / 128, NEXP), 256, SMEM1>>>(
        (const __half*)p_xg, (const __half*)p_w1h, b1);
    gemm_tc<HID, DIM, 128, 1, 2><<<dim3(DIM / 128, NASSIGN / 128, NEXP), 256, SMEM2>>>(
        (const __half*)p_hb, (const __half*)p_w2h, b2);
    combine_kernel<<<(NTOK * DIM / 4) / 256, 256>>>(out_final);
}